// round 15
// baseline (speedup 1.0000x reference)
#include <cuda_runtime.h>
#include <stdint.h>
#include <math.h>

// Problem constants
#define BB 8
#define NN 262144
#define CC 23
#define GG 10

#define THREADS 128
#define NWARPS (THREADS / 32)                 // 4
#define ITERS 8
#define ROWS_PER_BLOCK (THREADS * ITERS)      // 1024
#define CHUNKS (NN / ROWS_PER_BLOCK)          // 256
#define GRID (BB * CHUNKS)                    // 2048 -> fills 9 blocks/SM (1332 capacity)
#define TILE_FLOATS (THREADS * CC)            // 2944
#define TILE_VEC4 (TILE_FLOATS / 4)           // 736

// Scratch (no device allocation allowed -> static globals).
__device__ float g_partial[GRID * GG];        // 20480 floats
__device__ unsigned g_ticket;                 // zero-init; reset by last block

__device__ __forceinline__ unsigned smem_u32(const void* p) {
    unsigned a;
    asm("{ .reg .u64 t; cvta.to.shared.u64 t, %1; cvt.u32.u64 %0, t; }" : "=r"(a) : "l"(p));
    return a;
}

__global__ __launch_bounds__(THREADS, 9) void fused_kernel(const float* __restrict__ inp,
                                                           const float* __restrict__ targets,
                                                           float* __restrict__ out) {
    __shared__ float tile[2][TILE_FLOATS];     // 23552 B -> 9 blocks/SM
    __shared__ float wsum[NWARPS][GG];
    __shared__ float avg[BB * GG];
    __shared__ float klb[BB];
    __shared__ unsigned s_islast;

    const int tid = threadIdx.x;
    const int lane = tid & 31;
    const int warp = tid >> 5;
    const int b = blockIdx.x >> 8;        // / CHUNKS
    const int chunk = blockIdx.x & 255;   // % CHUNKS
    const size_t row_base = (size_t)b * NN + (size_t)chunk * ROWS_PER_BLOCK;

    const unsigned sbuf0 = smem_u32(&tile[0][0]);
    const unsigned sbuf1 = smem_u32(&tile[1][0]);

    auto issue_tile = [&](int it, int buf) {
        const float4* __restrict__ src =
            reinterpret_cast<const float4*>(inp + (row_base + (size_t)it * THREADS) * CC);
        const unsigned s = buf ? sbuf1 : sbuf0;
        #pragma unroll
        for (int i = tid; i < TILE_VEC4; i += THREADS) {
            asm volatile("cp.async.cg.shared.global [%0], [%1], 16;"
                         :: "r"(s + (unsigned)i * 16), "l"(src + i));
        }
        asm volatile("cp.async.commit_group;");
    };

    float a0 = 0.f, a1 = 0.f, a2 = 0.f, a3 = 0.f, a4 = 0.f;
    float a5 = 0.f, a6 = 0.f, a7 = 0.f, a8 = 0.f, a9 = 0.f;

    issue_tile(0, 0);

    for (int it = 0; it < ITERS; it++) {
        if (it + 1 < ITERS) {
            issue_tile(it + 1, (it + 1) & 1);
            asm volatile("cp.async.wait_group 1;");
        } else {
            asm volatile("cp.async.wait_group 0;");
        }
        __syncthreads();

        // One row per thread; stride-23 across lanes is bank-conflict-free.
        const float* row = &tile[it & 1][tid * CC];
        float v[CC];
        #pragma unroll
        for (int c = 0; c < CC; c++) v[c] = row[c];

        const float s0 = v[0] + v[1];
        const float s1 = v[2] + v[3];
        const float s2 = v[4] + v[5] + v[6];
        const float s3 = v[7] + v[8];
        const float s4 = v[9] + v[10] + v[11];
        const float s5 = v[12] + v[13];
        const float s6 = v[14] + v[15] + v[16];
        const float s7 = v[17] + v[18];
        const float s8 = v[19] + v[20];
        const float s9 = v[21] + v[22];

        const float total = ((s0 + s1) + (s2 + s3)) + ((s4 + s5) + (s6 + s7)) + (s8 + s9);
        const float inv = 1.0f / total;

        a0 += s0 * inv; a1 += s1 * inv; a2 += s2 * inv; a3 += s3 * inv; a4 += s4 * inv;
        a5 += s5 * inv; a6 += s6 * inv; a7 += s7 * inv; a8 += s8 * inv; a9 += s9 * inv;
        __syncthreads();   // buffer (it&1) safe to overwrite at next issue
    }

    // Block reduction: warp shuffle then per-warp SMEM (deterministic, no atomics).
    float acc[GG] = {a0, a1, a2, a3, a4, a5, a6, a7, a8, a9};
    #pragma unroll
    for (int g = 0; g < GG; g++) {
        float x = acc[g];
        x += __shfl_down_sync(0xffffffffu, x, 16);
        x += __shfl_down_sync(0xffffffffu, x, 8);
        x += __shfl_down_sync(0xffffffffu, x, 4);
        x += __shfl_down_sync(0xffffffffu, x, 2);
        x += __shfl_down_sync(0xffffffffu, x, 1);
        if (lane == 0) wsum[warp][g] = x;
    }
    __syncthreads();
    if (tid < GG) {
        float s = 0.f;
        #pragma unroll
        for (int w = 0; w < NWARPS; w++) s += wsum[w][tid];
        g_partial[blockIdx.x * GG + tid] = s;
    }

    // ---- last-block-done: final block reduces everything in-kernel ----
    __threadfence();
    if (tid == 0)
        s_islast = (atomicAdd(&g_ticket, 1u) == GRID - 1u);
    __syncthreads();
    if (!s_islast) return;
    __threadfence();

    // 80 (b,g) tasks over 4 warps -> 20 per warp; lane sums 8 partials (256 chunks).
    #pragma unroll
    for (int k = 0; k < 20; k++) {
        const int t = warp * 20 + k;             // 0..79
        const int tb = t / GG;
        const int tg = t % GG;
        const int blk0 = tb * CHUNKS;
        float x = 0.f;
        #pragma unroll
        for (int j = 0; j < CHUNKS / 32; j++)    // 8 independent loads
            x += g_partial[(blk0 + lane + 32 * j) * GG + tg];
        x += __shfl_down_sync(0xffffffffu, x, 16);
        x += __shfl_down_sync(0xffffffffu, x, 8);
        x += __shfl_down_sync(0xffffffffu, x, 4);
        x += __shfl_down_sync(0xffffffffu, x, 2);
        x += __shfl_down_sync(0xffffffffu, x, 1);
        if (lane == 0) avg[t] = x * (1.0f / (float)NN);
    }
    __syncthreads();

    if (tid < BB) {
        float kl = 0.f;
        #pragma unroll
        for (int g = 0; g < GG; g++) {
            const float tg = targets[tid * GG + g];
            kl += tg * (logf(tg) - logf(avg[tid * GG + g]));
        }
        klb[tid] = kl;
    }
    __syncthreads();

    if (tid == 0) {
        float s = 0.f;
        #pragma unroll
        for (int bb = 0; bb < BB; bb++) s += klb[bb];
        out[0] = s / (float)(GG * BB);
        g_ticket = 0;                            // reset for next graph replay
    }
}

extern "C" void kernel_launch(void* const* d_in, const int* in_sizes, int n_in,
                              void* d_out, int out_size) {
    const float* inp = (const float*)d_in[0];
    const float* tgt = (const float*)d_in[1];
    if (n_in >= 2 && in_sizes[0] == BB * GG) {   // defensive order check
        inp = (const float*)d_in[1];
        tgt = (const float*)d_in[0];
    }
    fused_kernel<<<GRID, THREADS>>>(inp, tgt, (float*)d_out);
}

// round 17
// speedup vs baseline: 1.1212x; 1.1212x over previous
#include <cuda_runtime.h>
#include <stdint.h>
#include <math.h>

// Problem constants
#define BB 8
#define NN 262144
#define CC 23
#define GG 10

#define THREADS 256
#define ITERS 8
#define ROWS_PER_BLOCK (THREADS * ITERS)      // 2048
#define CHUNKS (NN / ROWS_PER_BLOCK)          // 128
#define GRID (BB * CHUNKS)                    // 1024
#define TILE_FLOATS (THREADS * CC)            // 5888
#define TILE_BYTES (TILE_FLOATS * 4)          // 23552 (16B multiple)

// Scratch (no device allocation allowed -> static globals).
__device__ float g_partial[GRID * GG];
__device__ unsigned g_ticket;                 // zero-init; reset by last block

__device__ __forceinline__ unsigned smem_u32(const void* p) {
    unsigned a;
    asm("{ .reg .u64 t; cvta.to.shared.u64 t, %1; cvt.u32.u64 %0, t; }" : "=r"(a) : "l"(p));
    return a;
}

__device__ __forceinline__ void mbar_init(unsigned bar, unsigned count) {
    asm volatile("mbarrier.init.shared.b64 [%0], %1;" :: "r"(bar), "r"(count) : "memory");
}
__device__ __forceinline__ void mbar_expect_tx(unsigned bar, unsigned bytes) {
    asm volatile("mbarrier.arrive.expect_tx.shared.b64 _, [%0], %1;"
                 :: "r"(bar), "r"(bytes) : "memory");
}
__device__ __forceinline__ void bulk_ld(unsigned dst, const void* src, unsigned bytes, unsigned bar) {
    asm volatile("cp.async.bulk.shared::cta.global.mbarrier::complete_tx::bytes "
                 "[%0], [%1], %2, [%3];"
                 :: "r"(dst), "l"(src), "r"(bytes), "r"(bar) : "memory");
}
__device__ __forceinline__ void mbar_wait(unsigned bar, unsigned parity) {
    asm volatile(
        "{\n\t"
        ".reg .pred P;\n\t"
        "WL_%=:\n\t"
        "mbarrier.try_wait.parity.acquire.cta.shared::cta.b64 P, [%0], %1, 0x989680;\n\t"
        "@P bra.uni WD_%=;\n\t"
        "bra.uni WL_%=;\n\t"
        "WD_%=:\n\t"
        "}"
        :: "r"(bar), "r"(parity) : "memory");
}

__global__ __launch_bounds__(THREADS) void fused_kernel(const float* __restrict__ inp,
                                                        const float* __restrict__ targets,
                                                        float* __restrict__ out) {
    __shared__ float tile[2][TILE_FLOATS];          // 47104 B
    __shared__ __align__(8) unsigned long long bars[2];
    __shared__ float wsum[THREADS / 32][GG];
    __shared__ float avg[BB * GG];
    __shared__ float klb[BB];
    __shared__ unsigned s_islast;

    const int tid = threadIdx.x;
    const int lane = tid & 31;
    const int warp = tid >> 5;
    const int b = blockIdx.x >> 7;        // / CHUNKS
    const int chunk = blockIdx.x & 127;   // % CHUNKS
    const size_t row_base = (size_t)b * NN + (size_t)chunk * ROWS_PER_BLOCK;
    const float* const src_base = inp + row_base * CC;

    const unsigned sbuf0 = smem_u32(&tile[0][0]);
    const unsigned sbuf1 = smem_u32(&tile[1][0]);
    const unsigned bar0 = smem_u32(&bars[0]);
    const unsigned bar1 = smem_u32(&bars[1]);

    if (tid == 0) {
        mbar_init(bar0, 1);
        mbar_init(bar1, 1);
    }
    __syncthreads();

    // Prologue: tile 0 -> buf0, tile 1 -> buf1 (TMA bulk, single thread).
    if (tid == 0) {
        mbar_expect_tx(bar0, TILE_BYTES);
        bulk_ld(sbuf0, src_base, TILE_BYTES, bar0);
        mbar_expect_tx(bar1, TILE_BYTES);
        bulk_ld(sbuf1, src_base + (size_t)TILE_FLOATS, TILE_BYTES, bar1);
    }

    float a0 = 0.f, a1 = 0.f, a2 = 0.f, a3 = 0.f, a4 = 0.f;
    float a5 = 0.f, a6 = 0.f, a7 = 0.f, a8 = 0.f, a9 = 0.f;

    unsigned ph0 = 0, ph1 = 0;   // per-buffer phase parity

    for (int it = 0; it < ITERS; it++) {
        const int bsel = it & 1;
        const unsigned bar = bsel ? bar1 : bar0;
        // Wait for tile `it` in buffer bsel.
        if (bsel) { mbar_wait(bar, ph1); ph1 ^= 1; }
        else      { mbar_wait(bar, ph0); ph0 ^= 1; }

        // One row per thread; stride-23 across lanes is bank-conflict-free.
        const float* row = &tile[bsel][tid * CC];
        float v[CC];
        #pragma unroll
        for (int c = 0; c < CC; c++) v[c] = row[c];

        const float s0 = v[0] + v[1];
        const float s1 = v[2] + v[3];
        const float s2 = v[4] + v[5] + v[6];
        const float s3 = v[7] + v[8];
        const float s4 = v[9] + v[10] + v[11];
        const float s5 = v[12] + v[13];
        const float s6 = v[14] + v[15] + v[16];
        const float s7 = v[17] + v[18];
        const float s8 = v[19] + v[20];
        const float s9 = v[21] + v[22];

        const float total = ((s0 + s1) + (s2 + s3)) + ((s4 + s5) + (s6 + s7)) + (s8 + s9);
        const float inv = 1.0f / total;

        a0 += s0 * inv; a1 += s1 * inv; a2 += s2 * inv; a3 += s3 * inv; a4 += s4 * inv;
        a5 += s5 * inv; a6 += s6 * inv; a7 += s7 * inv; a8 += s8 * inv; a9 += s9 * inv;

        __syncthreads();   // all threads done reading buffer bsel
        if (it + 2 < ITERS && tid == 0) {
            mbar_expect_tx(bar, TILE_BYTES);
            bulk_ld(bsel ? sbuf1 : sbuf0,
                    src_base + (size_t)(it + 2) * TILE_FLOATS, TILE_BYTES, bar);
        }
    }

    // Block reduction: warp shuffle then per-warp SMEM (deterministic, no atomics).
    float acc[GG] = {a0, a1, a2, a3, a4, a5, a6, a7, a8, a9};
    #pragma unroll
    for (int g = 0; g < GG; g++) {
        float x = acc[g];
        x += __shfl_down_sync(0xffffffffu, x, 16);
        x += __shfl_down_sync(0xffffffffu, x, 8);
        x += __shfl_down_sync(0xffffffffu, x, 4);
        x += __shfl_down_sync(0xffffffffu, x, 2);
        x += __shfl_down_sync(0xffffffffu, x, 1);
        if (lane == 0) wsum[warp][g] = x;
    }
    __syncthreads();
    if (tid < GG) {
        float s = 0.f;
        #pragma unroll
        for (int w = 0; w < THREADS / 32; w++) s += wsum[w][tid];
        g_partial[blockIdx.x * GG + tid] = s;
    }

    // ---- last-block-done: final block reduces everything in-kernel ----
    __threadfence();
    if (tid == 0)
        s_islast = (atomicAdd(&g_ticket, 1u) == GRID - 1u);
    __syncthreads();
    if (!s_islast) return;
    __threadfence();

    // 80 (b,g) tasks over 8 warps -> 10 per warp; lane sums 4 partials (128 chunks).
    #pragma unroll
    for (int k = 0; k < GG; k++) {
        const int t = warp * GG + k;             // 0..79
        const int tb = t / GG;
        const int tg = t % GG;
        const int blk0 = tb * CHUNKS;
        float x = g_partial[(blk0 + lane +  0) * GG + tg]
                + g_partial[(blk0 + lane + 32) * GG + tg]
                + g_partial[(blk0 + lane + 64) * GG + tg]
                + g_partial[(blk0 + lane + 96) * GG + tg];
        x += __shfl_down_sync(0xffffffffu, x, 16);
        x += __shfl_down_sync(0xffffffffu, x, 8);
        x += __shfl_down_sync(0xffffffffu, x, 4);
        x += __shfl_down_sync(0xffffffffu, x, 2);
        x += __shfl_down_sync(0xffffffffu, x, 1);
        if (lane == 0) avg[t] = x * (1.0f / (float)NN);
    }
    __syncthreads();

    if (tid < BB) {
        float kl = 0.f;
        #pragma unroll
        for (int g = 0; g < GG; g++) {
            const float tg = targets[tid * GG + g];
            kl += tg * (logf(tg) - logf(avg[tid * GG + g]));
        }
        klb[tid] = kl;
    }
    __syncthreads();

    if (tid == 0) {
        float s = 0.f;
        #pragma unroll
        for (int bb = 0; bb < BB; bb++) s += klb[bb];
        out[0] = s / (float)(GG * BB);
        g_ticket = 0;                            // reset for next graph replay
    }
}

extern "C" void kernel_launch(void* const* d_in, const int* in_sizes, int n_in,
                              void* d_out, int out_size) {
    const float* inp = (const float*)d_in[0];
    const float* tgt = (const float*)d_in[1];
    if (n_in >= 2 && in_sizes[0] == BB * GG) {   // defensive order check
        inp = (const float*)d_in[1];
        tgt = (const float*)d_in[0];
    }
    fused_kernel<<<GRID, THREADS>>>(inp, tgt, (float*)d_out);
}